// round 3
// baseline (speedup 1.0000x reference)
#include <cuda_runtime.h>

// VN_Attention: B=8, C=64, U=3, N=512
// R3: grid = (512, 2). Two CTAs per (b,c), split by query half, to raise
// occupancy (512 CTAs was only 3.46/SM -> 20 warps -> latency-bound at ~50%
// on every pipe). Each CTA recomputes the full q,k,v projection (cheap,
// prefetchable); phase 2 handles 256 queries, one per thread, f32x2 packed
// across adjacent keys.

#define BB 8
#define CC 64
#define UU 3
#define NN 512
#define THREADS 256
#define SLAB (UU * NN)          // 1536 floats per (b,c) slab
#define SLAB2 (SLAB / 2)        // 768 float2/ull

typedef unsigned long long ull;

__device__ __forceinline__ float ex2_approx(float x) {
    float r;
    asm("ex2.approx.ftz.f32 %0, %1;" : "=f"(r) : "f"(x));
    return r;
}
__device__ __forceinline__ ull pack2(float lo, float hi) {
    ull r; asm("mov.b64 %0, {%1, %2};" : "=l"(r) : "f"(lo), "f"(hi)); return r;
}
__device__ __forceinline__ void unpack2(ull v, float& lo, float& hi) {
    asm("mov.b64 {%0, %1}, %2;" : "=f"(lo), "=f"(hi) : "l"(v));
}
__device__ __forceinline__ ull fma2(ull a, ull b, ull c) {
    ull d; asm("fma.rn.f32x2 %0, %1, %2, %3;" : "=l"(d) : "l"(a), "l"(b), "l"(c)); return d;
}
__device__ __forceinline__ ull mul2(ull a, ull b) {
    ull d; asm("mul.rn.f32x2 %0, %1, %2;" : "=l"(d) : "l"(a), "l"(b)); return d;
}
__device__ __forceinline__ ull add2(ull a, ull b) {
    ull d; asm("add.rn.f32x2 %0, %1, %2;" : "=l"(d) : "l"(a), "l"(b)); return d;
}

__global__ __launch_bounds__(THREADS, 5)
void vn_attention_kernel(const float* __restrict__ x,
                         const float* __restrict__ Wq,
                         const float* __restrict__ Wk,
                         const float* __restrict__ Wv,
                         float* __restrict__ out)
{
    __shared__ float wq[CC], wk[CC], wv[CC];
    __shared__ float qsm[UU][NN];                 // 6 KB
    __shared__ __align__(16) float kv[256 * 12];  // 12 KB: j-pair row = 6 float2

    const int tid = threadIdx.x;
    const int b = blockIdx.x >> 6;
    const int c = blockIdx.x & 63;

    if (tid < CC) {
        wq[tid] = Wq[c * CC + tid];
        wk[tid] = Wk[c * CC + tid];
        wv[tid] = Wv[c * CC + tid];
    }
    __syncthreads();

    // ---- Phase 1: full q,k,v projection, packed f32x2. Thread owns float2
    // index p = tid + 256r (r=0..2): u = p>>8, pair-index = p&255.
    ull aq[3], ak[3], av[3];
    #pragma unroll
    for (int r = 0; r < 3; ++r) { aq[r] = 0ull; ak[r] = 0ull; av[r] = 0ull; }

    const ull* xb = reinterpret_cast<const ull*>(x) + (size_t)b * CC * SLAB2;
    #pragma unroll 4
    for (int cp = 0; cp < CC; ++cp) {
        const ull* xr = xb + cp * SLAB2;
        const ull wq2 = pack2(wq[cp], wq[cp]);
        const ull wk2 = pack2(wk[cp], wk[cp]);
        const ull wv2 = pack2(wv[cp], wv[cp]);
        #pragma unroll
        for (int r = 0; r < 3; ++r) {
            ull xv = xr[tid + r * THREADS];
            aq[r] = fma2(xv, wq2, aq[r]);
            ak[r] = fma2(xv, wk2, ak[r]);
            av[r] = fma2(xv, wv2, av[r]);
        }
    }

    // Stage: q as [u][n]; k,v interleaved per j-pair row (6 float2 = 48B).
    ull* qsmU = reinterpret_cast<ull*>(&qsm[0][0]);
    ull* kvU  = reinterpret_cast<ull*>(kv);
    #pragma unroll
    for (int r = 0; r < 3; ++r) {
        qsmU[tid + r * THREADS] = aq[r];
        kvU[tid * 6 + r]     = ak[r];
        kvU[tid * 6 + 3 + r] = av[r];
    }
    __syncthreads();

    // ---- Phase 2: this CTA's query half, 1 query per thread.
    const float qs = 0.125f * 1.44269504088896340736f;  // C^-0.5 * log2(e)
    const int i = blockIdx.y * THREADS + tid;

    const ull q0 = pack2(qsm[0][i] * qs, qsm[0][i] * qs);
    const ull q1 = pack2(qsm[1][i] * qs, qsm[1][i] * qs);
    const ull q2 = pack2(qsm[2][i] * qs, qsm[2][i] * qs);

    ull s = 0ull, a0 = 0ull, a1 = 0ull, a2 = 0ull;

    const ulonglong2* kvrow = reinterpret_cast<const ulonglong2*>(kv);
    #pragma unroll 8
    for (int p = 0; p < 256; ++p) {
        // row p: A=(k0,k1), B=(k2, v0), C=(v1, v2)  (each component a j-pair)
        const ulonglong2 A = kvrow[p * 3 + 0];
        const ulonglong2 B = kvrow[p * 3 + 1];
        const ulonglong2 C = kvrow[p * 3 + 2];

        ull d = fma2(q0, A.x, fma2(q1, A.y, mul2(q2, B.x)));
        float dl, dh;
        unpack2(d, dl, dh);
        const ull e = pack2(ex2_approx(dl), ex2_approx(dh));

        s  = add2(s, e);
        a0 = fma2(e, B.y, a0);
        a1 = fma2(e, C.x, a1);
        a2 = fma2(e, C.y, a2);
    }

    float lo, hi;
    float sf;
    unpack2(s, lo, hi); sf = lo + hi;
    const float inv = __fdividef(1.f, sf);

    float r0, r1, r2;
    unpack2(a0, lo, hi); r0 = lo + hi;
    unpack2(a1, lo, hi); r1 = lo + hi;
    unpack2(a2, lo, hi); r2 = lo + hi;

    const size_t base = (size_t)(b * CC + c) * SLAB;
    out[base + 0 * NN + i] = x[base + 0 * NN + i] + r0 * inv;
    out[base + 1 * NN + i] = x[base + 1 * NN + i] + r1 * inv;
    out[base + 2 * NN + i] = x[base + 2 * NN + i] + r2 * inv;
}

extern "C" void kernel_launch(void* const* d_in, const int* in_sizes, int n_in,
                              void* d_out, int out_size) {
    const float* x  = (const float*)d_in[0];
    const float* Wq = (const float*)d_in[1];
    const float* Wk = (const float*)d_in[2];
    const float* Wv = (const float*)d_in[3];
    float* out = (float*)d_out;
    dim3 grid(BB * CC, 2);
    vn_attention_kernel<<<grid, THREADS>>>(x, Wq, Wk, Wv, out);
}

// round 4
// speedup vs baseline: 1.0639x; 1.0639x over previous
#include <cuda_runtime.h>

// VN_Attention: B=8, C=64, U=3, N=512
// R4: 128-thread CTAs, grid (512, 2) split by query half, 2 queries/thread.
// Keeps the q=2 LDS amortization (3 broadcast LDS.128 per j-pair serve 2
// queries) that R3 lost, while doubling CTA count for finer SM packing.
// Each CTA recomputes the full q,k,v projection (phase-1 dup ~8% busy, and
// its x re-reads are L1-hits since same-b CTAs stream the same slab).

#define BB 8
#define CC 64
#define UU 3
#define NN 512
#define THREADS 128
#define SLAB (UU * NN)          // 1536 floats per (b,c) slab
#define SLAB2 (SLAB / 2)        // 768 float2/ull

typedef unsigned long long ull;

__device__ __forceinline__ float ex2_approx(float x) {
    float r;
    asm("ex2.approx.ftz.f32 %0, %1;" : "=f"(r) : "f"(x));
    return r;
}
__device__ __forceinline__ ull pack2(float lo, float hi) {
    ull r; asm("mov.b64 %0, {%1, %2};" : "=l"(r) : "f"(lo), "f"(hi)); return r;
}
__device__ __forceinline__ void unpack2(ull v, float& lo, float& hi) {
    asm("mov.b64 {%0, %1}, %2;" : "=f"(lo), "=f"(hi) : "l"(v));
}
__device__ __forceinline__ ull fma2(ull a, ull b, ull c) {
    ull d; asm("fma.rn.f32x2 %0, %1, %2, %3;" : "=l"(d) : "l"(a), "l"(b), "l"(c)); return d;
}
__device__ __forceinline__ ull mul2(ull a, ull b) {
    ull d; asm("mul.rn.f32x2 %0, %1, %2;" : "=l"(d) : "l"(a), "l"(b)); return d;
}
__device__ __forceinline__ ull add2(ull a, ull b) {
    ull d; asm("add.rn.f32x2 %0, %1, %2;" : "=l"(d) : "l"(a), "l"(b)); return d;
}

__global__ __launch_bounds__(THREADS, 8)
void vn_attention_kernel(const float* __restrict__ x,
                         const float* __restrict__ Wq,
                         const float* __restrict__ Wk,
                         const float* __restrict__ Wv,
                         float* __restrict__ out)
{
    __shared__ float wq[CC], wk[CC], wv[CC];
    __shared__ float qsm[UU][NN];                 // 6 KB
    __shared__ __align__(16) float kv[256 * 12];  // 12 KB: j-pair row = 6 float2

    const int tid = threadIdx.x;
    const int b = blockIdx.x >> 6;
    const int c = blockIdx.x & 63;
    const int h = blockIdx.y;          // query half

    if (tid < CC) {
        wq[tid] = Wq[c * CC + tid];
        wk[tid] = Wk[c * CC + tid];
        wv[tid] = Wv[c * CC + tid];
    }
    __syncthreads();

    // ---- Phase 1: full q,k,v projection, packed f32x2.
    // Thread owns float2 positions p = tid + 128r, r = 0..5.
    ull aq[6], ak[6], av[6];
    #pragma unroll
    for (int r = 0; r < 6; ++r) { aq[r] = 0ull; ak[r] = 0ull; av[r] = 0ull; }

    const ull* xb = reinterpret_cast<const ull*>(x) + (size_t)b * CC * SLAB2;
    #pragma unroll 2
    for (int cp = 0; cp < CC; ++cp) {
        const ull* xr = xb + cp * SLAB2;
        const ull wq2 = pack2(wq[cp], wq[cp]);
        const ull wk2 = pack2(wk[cp], wk[cp]);
        const ull wv2 = pack2(wv[cp], wv[cp]);
        ull xv[6];
        #pragma unroll
        for (int r = 0; r < 6; ++r) xv[r] = xr[tid + r * THREADS];
        #pragma unroll
        for (int r = 0; r < 6; ++r) {
            aq[r] = fma2(xv[r], wq2, aq[r]);
            ak[r] = fma2(xv[r], wk2, ak[r]);
            av[r] = fma2(xv[r], wv2, av[r]);
        }
    }

    // Stage: q as [u][n]; k,v interleaved per j-pair row (6 float2 = 48B).
    ull* qsmU = reinterpret_cast<ull*>(&qsm[0][0]);
    ull* kvU  = reinterpret_cast<ull*>(kv);
    #pragma unroll
    for (int r = 0; r < 6; ++r) {
        const int p = tid + r * THREADS;   // float2 index in [0,768)
        qsmU[p] = aq[r];
        const int u  = p >> 8;             // 0..2
        const int pp = p & 255;            // j-pair index
        kvU[pp * 6 + u]     = ak[r];
        kvU[pp * 6 + 3 + u] = av[r];
    }
    __syncthreads();

    // ---- Phase 2: this CTA's query half, 2 queries per thread.
    const float qs = 0.125f * 1.44269504088896340736f;  // C^-0.5 * log2(e)
    const int i0 = h * 256 + tid;
    const int i1 = i0 + THREADS;

    const ull q00 = pack2(qsm[0][i0] * qs, qsm[0][i0] * qs);
    const ull q01 = pack2(qsm[1][i0] * qs, qsm[1][i0] * qs);
    const ull q02 = pack2(qsm[2][i0] * qs, qsm[2][i0] * qs);
    const ull q10 = pack2(qsm[0][i1] * qs, qsm[0][i1] * qs);
    const ull q11 = pack2(qsm[1][i1] * qs, qsm[1][i1] * qs);
    const ull q12 = pack2(qsm[2][i1] * qs, qsm[2][i1] * qs);

    ull s0 = 0ull, a00 = 0ull, a01 = 0ull, a02 = 0ull;
    ull s1 = 0ull, a10 = 0ull, a11 = 0ull, a12 = 0ull;

    const ulonglong2* kvrow = reinterpret_cast<const ulonglong2*>(kv);
    #pragma unroll 4
    for (int p = 0; p < 256; ++p) {
        // row p: A=(k0,k1), B=(k2,v0), C=(v1,v2)  (each component a j-pair)
        const ulonglong2 A = kvrow[p * 3 + 0];
        const ulonglong2 B = kvrow[p * 3 + 1];
        const ulonglong2 C = kvrow[p * 3 + 2];

        ull d0 = fma2(q00, A.x, fma2(q01, A.y, mul2(q02, B.x)));
        ull d1 = fma2(q10, A.x, fma2(q11, A.y, mul2(q12, B.x)));

        float d0l, d0h, d1l, d1h;
        unpack2(d0, d0l, d0h);
        unpack2(d1, d1l, d1h);
        const ull e0 = pack2(ex2_approx(d0l), ex2_approx(d0h));
        const ull e1 = pack2(ex2_approx(d1l), ex2_approx(d1h));

        s0 = add2(s0, e0);
        a00 = fma2(e0, B.y, a00);
        a01 = fma2(e0, C.x, a01);
        a02 = fma2(e0, C.y, a02);

        s1 = add2(s1, e1);
        a10 = fma2(e1, B.y, a10);
        a11 = fma2(e1, C.x, a11);
        a12 = fma2(e1, C.y, a12);
    }

    float lo, hi, s0f, s1f;
    unpack2(s0, lo, hi); s0f = lo + hi;
    unpack2(s1, lo, hi); s1f = lo + hi;
    const float inv0 = __fdividef(1.f, s0f);
    const float inv1 = __fdividef(1.f, s1f);

    float r00, r01, r02, r10, r11, r12;
    unpack2(a00, lo, hi); r00 = lo + hi;
    unpack2(a01, lo, hi); r01 = lo + hi;
    unpack2(a02, lo, hi); r02 = lo + hi;
    unpack2(a10, lo, hi); r10 = lo + hi;
    unpack2(a11, lo, hi); r11 = lo + hi;
    unpack2(a12, lo, hi); r12 = lo + hi;

    const size_t base = (size_t)(b * CC + c) * SLAB;
    out[base + 0 * NN + i0] = x[base + 0 * NN + i0] + r00 * inv0;
    out[base + 1 * NN + i0] = x[base + 1 * NN + i0] + r01 * inv0;
    out[base + 2 * NN + i0] = x[base + 2 * NN + i0] + r02 * inv0;
    out[base + 0 * NN + i1] = x[base + 0 * NN + i1] + r10 * inv1;
    out[base + 1 * NN + i1] = x[base + 1 * NN + i1] + r11 * inv1;
    out[base + 2 * NN + i1] = x[base + 2 * NN + i1] + r12 * inv1;
}

extern "C" void kernel_launch(void* const* d_in, const int* in_sizes, int n_in,
                              void* d_out, int out_size) {
    const float* x  = (const float*)d_in[0];
    const float* Wq = (const float*)d_in[1];
    const float* Wk = (const float*)d_in[2];
    const float* Wv = (const float*)d_in[3];
    float* out = (float*)d_out;
    dim3 grid(BB * CC, 2);
    vn_attention_kernel<<<grid, THREADS>>>(x, Wq, Wk, Wv, out);
}